// round 6
// baseline (speedup 1.0000x reference)
#include <cuda_runtime.h>
#include <cstdint>
#include <cstddef>

// ============================================================================
// MpCosineLayer: out[b,i,j,m] = tanh( sum_d v1[b,i,d]*kernel[m,d]*v2[b,j,d] )
// B=64, T1=128, T2=160, D=768, M=64.  Output fp32, 83,886,080 elements.
//
// Strategy: per CTA = (b, group of 4 m, group of 80 j).
//   A_mm[i,d] = rna_tf32(v1[b,i,d]*kernel[m,d])  built on CUDA cores -> SMEM
//   Btile[j,d] = rna_tf32(v2[b,j,d])             -> SMEM
//   tcgen05.mma kind::tf32 SS, M=128 N=80 K=8, 4 accumulators in TMEM.
//   2-stage SMEM pipeline, MMA completion via tcgen05.commit -> mbarrier.
//   Epilogue: LDTM, tanh via ex2/rcp MUFU, float4 (m-quad) stores.
//
// The tcgen05 path is gated on __CUDA_ARCH_FEAT_SM103_ALL so the harness's
// secondary compute_103 (non-'a') PTX pass compiles a plain-CUDA fallback
// instead of aborting ptxas. At runtime the sm_103a cubin is selected.
// ============================================================================

namespace {
constexpr int kB  = 64;
constexpr int kT1 = 128;
constexpr int kT2 = 160;
constexpr int kD  = 768;
constexpr int kM  = 64;

constexpr int MCNT   = 4;          // m values per CTA
constexpr int NT     = 80;         // j values per CTA
constexpr int KC     = 32;         // K elems per chunk = 128 bytes (SW128 row)
constexpr int NCHUNK = kD / KC;    // 24
constexpr int KSTEPS = KC / 8;     // 4 tf32 K-steps per chunk

constexpr int A_TILE_B  = kT1 * 128;                 // 16384 B
constexpr int B_TILE_B  = NT * 128;                  // 10240 B
constexpr int STAGE_PAD = 76800;                     // >= 4*A + B, 1024-aligned

constexpr int OFF_TMEM   = 0;
constexpr int OFF_MBAR   = 16;                       // two 8B mbarriers
constexpr int OFF_KERN   = 1024;                     // 4*768*4 = 12288 B
constexpr int OFF_STAGE0 = 14336;                    // 1024-aligned
constexpr int SMEM_TOTAL = OFF_STAGE0 + 2 * STAGE_PAD;  // 167936 B

// idesc, kind::tf32: D=F32(1<<4), A=TF32(2<<7), B=TF32(2<<10), N/8<<17, M/16<<24
constexpr uint32_t IDESC =
    (1u << 4) | (2u << 7) | (2u << 10) | ((uint32_t)(NT / 8) << 17) | (8u << 24);

// SW128 SMEM descriptor base: layout=SW128, version=1(Blackwell), SBO=64, LBO=1
constexpr uint64_t DESC_BASE = 0x4000404000010000ULL;
}  // namespace

#define SW128(o) ((o) ^ (((o) >> 3) & 0x70))

#if defined(__CUDA_ARCH_FEAT_SM103_ALL) || defined(__CUDA_ARCH_FEAT_SM100_ALL)
#define MPC_HAS_TCGEN05 1
#else
#define MPC_HAS_TCGEN05 0
#endif

__device__ __forceinline__ uint32_t smem_u32(const void* p) {
    uint32_t a;
    asm("{ .reg .u64 t; cvta.to.shared.u64 t, %1; cvt.u32.u64 %0, t; }"
        : "=r"(a) : "l"(p));
    return a;
}
__device__ __forceinline__ uint32_t f2tf32(float x) {
    uint32_t r;
    asm("cvt.rna.tf32.f32 %0, %1;" : "=r"(r) : "f"(x));
    return r;
}
__device__ __forceinline__ void sts128(uint32_t a, uint32_t x, uint32_t y,
                                       uint32_t z, uint32_t w) {
    asm volatile("st.shared.v4.b32 [%0], {%1,%2,%3,%4};"
                 :: "r"(a), "r"(x), "r"(y), "r"(z), "r"(w) : "memory");
}
__device__ __forceinline__ float fast_tanh(float x) {
    // tanh(x) = 1 - 2/(e^{2x}+1); MUFU.EX2 + MUFU.RCP, ~1e-6 error, saturates
    // correctly to +/-1 on overflow/underflow.
    float e = __expf(2.0f * x);
    float r;
    asm("rcp.approx.f32 %0, %1;" : "=f"(r) : "f"(e + 1.0f));
    return fmaf(-2.0f, r, 1.0f);
}

#if MPC_HAS_TCGEN05
__device__ __forceinline__ bool elect_one() {
    uint32_t p;
    asm volatile("{ .reg .pred P; elect.sync _|P, 0xFFFFFFFF; selp.b32 %0, 1, 0, P; }"
                 : "=r"(p));
    return p != 0;
}
__device__ __forceinline__ uint64_t make_desc(uint32_t addr) {
    return DESC_BASE | ((uint64_t)(addr >> 4) & 0x3FFFULL);
}
__device__ __forceinline__ void mbar_init(uint32_t mb, uint32_t cnt) {
    asm volatile("mbarrier.init.shared.b64 [%0], %1;" :: "r"(mb), "r"(cnt) : "memory");
}
__device__ __forceinline__ void mbar_wait(uint32_t mb, uint32_t ph) {
    asm volatile(
        "{\n\t.reg .pred P;\n\t"
        "LW_%=:\n\t"
        "mbarrier.try_wait.parity.acquire.cta.shared::cta.b64 P, [%0], %1, 0x989680;\n\t"
        "@P bra.uni LD_%=;\n\t"
        "bra.uni LW_%=;\n\t"
        "LD_%=:\n\t}"
        :: "r"(mb), "r"(ph) : "memory");
}
__device__ __forceinline__ void mma_tf32(uint32_t d, uint64_t ad, uint64_t bd,
                                         uint32_t idesc, uint32_t acc) {
    asm volatile(
        "{\n\t.reg .pred p;\n\t"
        "setp.ne.u32 p, %5, 0;\n\t"
        "tcgen05.mma.cta_group::1.kind::tf32 [%0], %1, %2, %3, {%4,%4,%4,%4}, p;\n\t}"
        :: "r"(d), "l"(ad), "l"(bd), "r"(idesc), "r"(0u), "r"(acc) : "memory");
}
__device__ __forceinline__ void tc_commit(uint32_t mb) {
    asm volatile(
        "tcgen05.commit.cta_group::1.mbarrier::arrive::one.shared::cluster.b64 [%0];"
        :: "r"(mb) : "memory");
}
__device__ __forceinline__ void ldtm_x8(uint32_t* r, uint32_t a) {
    asm volatile(
        "tcgen05.ld.sync.aligned.32x32b.x8.b32 {%0,%1,%2,%3,%4,%5,%6,%7}, [%8];"
        : "=r"(r[0]), "=r"(r[1]), "=r"(r[2]), "=r"(r[3]),
          "=r"(r[4]), "=r"(r[5]), "=r"(r[6]), "=r"(r[7])
        : "r"(a));
}
#endif  // MPC_HAS_TCGEN05

__global__ void __launch_bounds__(256, 1)
mpc_kernel(const float* __restrict__ v1, const float* __restrict__ v2,
           const float* __restrict__ kern, float* __restrict__ out) {
    extern __shared__ char smem[];
    const int tid = threadIdx.x;

    const int bid = blockIdx.x;
    const int jt = bid & 1;            // j-tile: 0 or 1 (80 each)
    const int mg = (bid >> 1) & 15;    // m-group: 4 m each
    const int b  = bid >> 5;           // batch

#if MPC_HAS_TCGEN05
    const uint32_t sb = smem_u32(smem);
    const int wid = tid >> 5;
    const int lane = tid & 31;

    // ---- TMEM alloc (warp 0), others relinquish ----
    if (wid == 0) {
        asm volatile("tcgen05.alloc.cta_group::1.sync.aligned.shared::cta.b32 [%0], %1;"
                     :: "r"(sb + OFF_TMEM), "r"(512u) : "memory");
    } else {
        asm volatile("tcgen05.relinquish_alloc_permit.cta_group::1.sync.aligned;");
    }

    // ---- preload this CTA's 4 kernel rows into SMEM (raw fp32) ----
    {
        float* ks = (float*)(smem + OFF_KERN);
        for (int i = tid; i < MCNT * kD; i += 256)
            ks[i] = kern[(size_t)(mg * MCNT + i / kD) * kD + (i % kD)];
    }
    if (tid == 0) {
        mbar_init(sb + OFF_MBAR + 0, 1);
        mbar_init(sb + OFF_MBAR + 8, 1);
    }
    __syncthreads();

    uint32_t tmem;
    asm volatile("ld.shared.b32 %0, [%1];" : "=r"(tmem) : "r"(sb + OFF_TMEM));

    // Thread mapping for A loads: g = 16B column group (0..7), base row = tid>>3,
    // covering rows base, base+32, base+64, base+96 (conflict-free SW128 STS).
    const int g  = tid & 7;
    const int rb = tid >> 3;  // 0..31
    const float* kq = (const float*)(smem + OFF_KERN);

    uint32_t ph0 = 0, ph1 = 0;

    for (int kc = 0; kc < NCHUNK; kc++) {
        const int s = kc & 1;
        if (kc >= 2) {
            if (s == 0) { mbar_wait(sb + OFF_MBAR + 0, ph0); ph0 ^= 1; }
            else        { mbar_wait(sb + OFF_MBAR + 8, ph1); ph1 ^= 1; }
        }
        const uint32_t stBase = sb + OFF_STAGE0 + (uint32_t)s * STAGE_PAD;

        // kernel quad for this column group, per m
        float4 kf[MCNT];
        #pragma unroll
        for (int mm = 0; mm < MCNT; mm++)
            kf[mm] = *(const float4*)(kq + mm * kD + kc * KC + g * 4);

        // ---- A tiles: 4 rows per thread, scaled by each of 4 kernel rows ----
        const float* v1p = v1 + ((size_t)b * kT1 + rb) * kD + kc * KC + g * 4;
        #pragma unroll
        for (int rr = 0; rr < 4; rr++) {
            float4 v = *(const float4*)(v1p + (size_t)rr * 32 * kD);
            const int row = rb + rr * 32;
            const uint32_t so = SW128((uint32_t)(row * 128 + g * 16));
            #pragma unroll
            for (int mm = 0; mm < MCNT; mm++) {
                sts128(stBase + mm * A_TILE_B + so,
                       f2tf32(v.x * kf[mm].x), f2tf32(v.y * kf[mm].y),
                       f2tf32(v.z * kf[mm].z), f2tf32(v.w * kf[mm].w));
            }
        }

        // ---- B tile: 80 rows x 8 groups = 640 float4 ----
        for (int idx = tid; idx < NT * 8; idx += 256) {
            const int j = idx >> 3, gg = idx & 7;
            float4 v = *(const float4*)(v2 + ((size_t)b * kT2 + jt * NT + j) * kD +
                                        kc * KC + gg * 4);
            sts128(stBase + MCNT * A_TILE_B + SW128((uint32_t)(j * 128 + gg * 16)),
                   f2tf32(v.x), f2tf32(v.y), f2tf32(v.z), f2tf32(v.w));
        }

        // make generic SMEM writes visible to the async (tensor) proxy
        asm volatile("fence.proxy.async.shared::cta;" ::: "memory");
        __syncthreads();

        // ---- issue 16 MMAs (4 K-steps x 4 m) from one thread ----
        if (wid == 0 && elect_one()) {
            const uint64_t bdesc = make_desc(stBase + MCNT * A_TILE_B);
            #pragma unroll
            for (int ks = 0; ks < KSTEPS; ks++) {
                #pragma unroll
                for (int mm = 0; mm < MCNT; mm++) {
                    mma_tf32(tmem + mm * NT,
                             make_desc(stBase + mm * A_TILE_B) + ks * 2,
                             bdesc + ks * 2, IDESC,
                             (kc > 0 || ks > 0) ? 1u : 0u);
                }
            }
            tc_commit(sb + OFF_MBAR + (uint32_t)s * 8);
        }
    }

    // ---- drain both stages ----
    mbar_wait(sb + OFF_MBAR + 0, ph0);
    mbar_wait(sb + OFF_MBAR + 8, ph1);
    asm volatile("tcgen05.fence::after_thread_sync;" ::: "memory");
    __syncthreads();

    // ---- epilogue ----
    // warp w: subpartition sp = w&3 -> rows i = sp*32+lane; j-half h = w>>2.
    // Each thread gathers all 4 m accumulators for its (i,j) -> float4 store.
    {
        const int sp = wid & 3;
        const int h  = wid >> 2;
        const uint32_t woff = ((uint32_t)sp) << 21;  // lane-base (sp*32)<<16
        const int i = sp * 32 + lane;
        float* obase = out + (((size_t)b * kT1 + i) * kT2 + (size_t)jt * NT) * kM +
                       (size_t)mg * MCNT;
        for (int jc = 0; jc < 5; jc++) {
            uint32_t acc[MCNT][8];
            #pragma unroll
            for (int mm = 0; mm < MCNT; mm++)
                ldtm_x8(acc[mm], tmem + mm * NT + h * 40 + jc * 8 + woff);
            asm volatile("tcgen05.wait::ld.sync.aligned;" ::: "memory");
            #pragma unroll
            for (int jj = 0; jj < 8; jj++) {
                const int j = h * 40 + jc * 8 + jj;
                float4 o;
                o.x = fast_tanh(__uint_as_float(acc[0][jj]));
                o.y = fast_tanh(__uint_as_float(acc[1][jj]));
                o.z = fast_tanh(__uint_as_float(acc[2][jj]));
                o.w = fast_tanh(__uint_as_float(acc[3][jj]));
                *(float4*)(obase + (size_t)j * kM) = o;
            }
        }
    }

    asm volatile("tcgen05.fence::before_thread_sync;" ::: "memory");
    __syncthreads();
    if (wid == 0) {
        asm volatile("tcgen05.dealloc.cta_group::1.sync.aligned.b32 %0, %1;"
                     :: "r"(tmem), "r"(512u));
    }

#else  // ---------------- non-sm_103a fallback (compiled, never run) --------
    // Same CTA tiling: (b, 4 m, 80 j). Kernel rows cached in SMEM; each thread
    // walks (i,j) pairs, 768-FMA loop per pair, tf32-rounded inputs to match.
    float* ks = (float*)(smem + OFF_KERN);
    for (int i = tid; i < MCNT * kD; i += 256)
        ks[i] = kern[(size_t)(mg * MCNT + i / kD) * kD + (i % kD)];
    __syncthreads();

    for (int idx = tid; idx < kT1 * NT; idx += 256) {
        const int i = idx / NT;
        const int j = jt * NT + idx % NT;
        const float* p1 = v1 + ((size_t)b * kT1 + i) * kD;
        const float* p2 = v2 + ((size_t)b * kT2 + j) * kD;
        float acc[MCNT] = {0.f, 0.f, 0.f, 0.f};
        for (int d = 0; d < kD; d++) {
            const float a = p1[d], c = p2[d];
            #pragma unroll
            for (int mm = 0; mm < MCNT; mm++)
                acc[mm] = fmaf(__uint_as_float(f2tf32(a * ks[mm * kD + d])),
                               __uint_as_float(f2tf32(c)), acc[mm]);
        }
        float* o = out + (((size_t)b * kT1 + i) * kT2 + j) * kM + (size_t)mg * MCNT;
        #pragma unroll
        for (int mm = 0; mm < MCNT; mm++) o[mm] = fast_tanh(acc[mm]);
    }
#endif
}

extern "C" void kernel_launch(void* const* d_in, const int* in_sizes, int n_in,
                              void* d_out, int out_size) {
    (void)in_sizes; (void)n_in; (void)out_size;
    const float* v1   = (const float*)d_in[0];
    const float* v2   = (const float*)d_in[1];
    const float* kern = (const float*)d_in[2];
    float* out = (float*)d_out;

    cudaFuncSetAttribute(mpc_kernel, cudaFuncAttributeMaxDynamicSharedMemorySize,
                         SMEM_TOTAL);
    // grid: b (64) x m-group (16) x j-tile (2) = 2048 CTAs; consecutive CTAs
    // share b -> v1/v2 stay L2-resident across the m-groups.
    mpc_kernel<<<2048, 256, SMEM_TOTAL>>>(v1, v2, kern, out);
}

// round 16
// speedup vs baseline: 1.6404x; 1.6404x over previous
#include <cuda_runtime.h>
#include <cstdint>
#include <cstddef>

// ============================================================================
// MpCosineLayer: out[b,i,j,m] = tanh( sum_d v1[b,i,d]*kernel[m,d]*v2[b,j,d] )
// B=64, T1=128, T2=160, D=768, M=64.  Output fp32, 83,886,080 elements.
//
// R12 = R11 resubmitted verbatim (R11 hit a broker-side container failure,
// never compiled/ran; nothing to update).
//
// kind::f16 rationale: fp16 has the SAME 10-bit mantissa as tf32 -> identical
// ~3e-4 rel_err, but runs the full-rate half-precision tensor path (tf32 is
// cut on Blackwell Ultra) and halves operand bytes (K=64 elems per 128B SW128
// row, 12 chunks instead of 24, half the STS/LDG work).
//
// Per CTA = (b, 4 m, 80 j):
//   A_mm[i,d] = f16(v1[b,i,d]*kernel[m,d])  built on CUDA cores -> SMEM
//   Btile[j,d] = f16(v2[b,j,d])             -> SMEM
//   tcgen05.mma kind::f16 SS, M=128 N=80 K=16, 4 accumulators in TMEM.
//   2-stage SMEM pipeline, MMA completion via tcgen05.commit -> mbarrier.
//   Epilogue: LDTM, tanh via ex2/rcp MUFU, float4 (m-quad) stores.
//
// tcgen05 path gated on __CUDA_ARCH_FEAT_SM103_ALL so the harness's secondary
// compute_103 (non-'a') PTX pass compiles a plain-CUDA fallback instead of
// aborting ptxas. At runtime the sm_103a cubin is selected.
// ============================================================================

namespace {
constexpr int kB  = 64;
constexpr int kT1 = 128;
constexpr int kT2 = 160;
constexpr int kD  = 768;
constexpr int kM  = 64;

constexpr int MCNT   = 4;          // m values per CTA
constexpr int NT     = 80;         // j values per CTA
constexpr int KC     = 64;         // K elems per chunk = 128 bytes (SW128 row)
constexpr int NCHUNK = kD / KC;    // 12
constexpr int KSTEPS = KC / 16;    // 4 f16 K-steps (K=16 each) per chunk

constexpr int A_TILE_B  = kT1 * 128;                 // 16384 B (128 rows x 128B)
constexpr int B_TILE_B  = NT * 128;                  // 10240 B
constexpr int STAGE_PAD = 76800;                     // >= 4*A + B, 1024-aligned

constexpr int OFF_TMEM   = 0;
constexpr int OFF_MBAR   = 16;                       // two 8B mbarriers
constexpr int OFF_KERN   = 1024;                     // 4*768*4 = 12288 B fp32
constexpr int OFF_STAGE0 = 14336;                    // 1024-aligned
constexpr int SMEM_TOTAL = OFF_STAGE0 + 2 * STAGE_PAD;  // 167936 B

// idesc, kind::f16: D=F32(1<<4), A=F16(0<<7), B=F16(0<<10), N/8<<17, M/16<<24
constexpr uint32_t IDESC =
    (1u << 4) | ((uint32_t)(NT / 8) << 17) | (8u << 24);

// SW128 SMEM descriptor base: layout=SW128, version=1(Blackwell), SBO=64, LBO=1
constexpr uint64_t DESC_BASE = 0x4000404000010000ULL;
}  // namespace

#define SW128(o) ((o) ^ (((o) >> 3) & 0x70))

#if defined(__CUDA_ARCH_FEAT_SM103_ALL) || defined(__CUDA_ARCH_FEAT_SM100_ALL)
#define MPC_HAS_TCGEN05 1
#else
#define MPC_HAS_TCGEN05 0
#endif

__device__ __forceinline__ uint32_t smem_u32(const void* p) {
    uint32_t a;
    asm("{ .reg .u64 t; cvta.to.shared.u64 t, %1; cvt.u32.u64 %0, t; }"
        : "=r"(a) : "l"(p));
    return a;
}
// pack two fp32 -> f16x2, lo = first arg, hi = second arg
__device__ __forceinline__ uint32_t f16x2(float lo, float hi) {
    uint32_t r;
    asm("cvt.rn.f16x2.f32 %0, %1, %2;" : "=r"(r) : "f"(hi), "f"(lo));
    return r;
}
// fp32 -> f16(rn) -> fp32 round-trip, no cuda_fp16.h needed
__device__ __forceinline__ float f16rt(float x) {
    float r;
    asm("{ .reg .b16 h; cvt.rn.f16.f32 h, %1; cvt.f32.f16 %0, h; }"
        : "=f"(r) : "f"(x));
    return r;
}
__device__ __forceinline__ void sts128(uint32_t a, uint32_t x, uint32_t y,
                                       uint32_t z, uint32_t w) {
    asm volatile("st.shared.v4.b32 [%0], {%1,%2,%3,%4};"
                 :: "r"(a), "r"(x), "r"(y), "r"(z), "r"(w) : "memory");
}
__device__ __forceinline__ float fast_tanh(float x) {
    // tanh(x) = 1 - 2/(e^{2x}+1); MUFU.EX2 + MUFU.RCP, ~1e-6 error, saturates
    // correctly to +/-1 on overflow/underflow.
    float e = __expf(2.0f * x);
    float r;
    asm("rcp.approx.f32 %0, %1;" : "=f"(r) : "f"(e + 1.0f));
    return fmaf(-2.0f, r, 1.0f);
}

#if MPC_HAS_TCGEN05
__device__ __forceinline__ bool elect_one() {
    uint32_t p;
    asm volatile("{ .reg .pred P; elect.sync _|P, 0xFFFFFFFF; selp.b32 %0, 1, 0, P; }"
                 : "=r"(p));
    return p != 0;
}
__device__ __forceinline__ uint64_t make_desc(uint32_t addr) {
    return DESC_BASE | ((uint64_t)(addr >> 4) & 0x3FFFULL);
}
__device__ __forceinline__ void mbar_init(uint32_t mb, uint32_t cnt) {
    asm volatile("mbarrier.init.shared.b64 [%0], %1;" :: "r"(mb), "r"(cnt) : "memory");
}
__device__ __forceinline__ void mbar_wait(uint32_t mb, uint32_t ph) {
    asm volatile(
        "{\n\t.reg .pred P;\n\t"
        "LW_%=:\n\t"
        "mbarrier.try_wait.parity.acquire.cta.shared::cta.b64 P, [%0], %1, 0x989680;\n\t"
        "@P bra.uni LD_%=;\n\t"
        "bra.uni LW_%=;\n\t"
        "LD_%=:\n\t}"
        :: "r"(mb), "r"(ph) : "memory");
}
__device__ __forceinline__ void mma_f16(uint32_t d, uint64_t ad, uint64_t bd,
                                        uint32_t idesc, uint32_t acc) {
    asm volatile(
        "{\n\t.reg .pred p;\n\t"
        "setp.ne.u32 p, %5, 0;\n\t"
        "tcgen05.mma.cta_group::1.kind::f16 [%0], %1, %2, %3, {%4,%4,%4,%4}, p;\n\t}"
        :: "r"(d), "l"(ad), "l"(bd), "r"(idesc), "r"(0u), "r"(acc) : "memory");
}
__device__ __forceinline__ void tc_commit(uint32_t mb) {
    asm volatile(
        "tcgen05.commit.cta_group::1.mbarrier::arrive::one.shared::cluster.b64 [%0];"
        :: "r"(mb) : "memory");
}
__device__ __forceinline__ void ldtm_x8(uint32_t* r, uint32_t a) {
    asm volatile(
        "tcgen05.ld.sync.aligned.32x32b.x8.b32 {%0,%1,%2,%3,%4,%5,%6,%7}, [%8];"
        : "=r"(r[0]), "=r"(r[1]), "=r"(r[2]), "=r"(r[3]),
          "=r"(r[4]), "=r"(r[5]), "=r"(r[6]), "=r"(r[7])
        : "r"(a));
}
#endif  // MPC_HAS_TCGEN05

__global__ void __launch_bounds__(256, 1)
mpc_kernel(const float* __restrict__ v1, const float* __restrict__ v2,
           const float* __restrict__ kern, float* __restrict__ out) {
    extern __shared__ char smem[];
    const int tid = threadIdx.x;

    const int bid = blockIdx.x;
    const int jt = bid & 1;            // j-tile: 0 or 1 (80 each)
    const int mg = (bid >> 1) & 15;    // m-group: 4 m each
    const int b  = bid >> 5;           // batch

#if MPC_HAS_TCGEN05
    const uint32_t sb = smem_u32(smem);
    const int wid = tid >> 5;
    const int lane = tid & 31;

    // ---- TMEM alloc (warp 0), others relinquish ----
    if (wid == 0) {
        asm volatile("tcgen05.alloc.cta_group::1.sync.aligned.shared::cta.b32 [%0], %1;"
                     :: "r"(sb + OFF_TMEM), "r"(512u) : "memory");
    } else {
        asm volatile("tcgen05.relinquish_alloc_permit.cta_group::1.sync.aligned;");
    }

    // ---- preload this CTA's 4 kernel rows into SMEM (raw fp32) ----
    {
        float* ks = (float*)(smem + OFF_KERN);
        for (int i = tid; i < MCNT * kD; i += 256)
            ks[i] = kern[(size_t)(mg * MCNT + i / kD) * kD + (i % kD)];
    }
    if (tid == 0) {
        mbar_init(sb + OFF_MBAR + 0, 1);
        mbar_init(sb + OFF_MBAR + 8, 1);
    }
    __syncthreads();

    uint32_t tmem;
    asm volatile("ld.shared.b32 %0, [%1];" : "=r"(tmem) : "r"(sb + OFF_TMEM));

    // A-tile thread mapping: g = 16B segment (8 f16 <- 8 fp32 source) in row,
    // base row rb = tid>>3; thread covers rows rb, rb+32, rb+64, rb+96.
    const int g  = tid & 7;
    const int rb = tid >> 3;  // 0..31
    const float* kq = (const float*)(smem + OFF_KERN);

    uint32_t ph0 = 0, ph1 = 0;

    for (int kc = 0; kc < NCHUNK; kc++) {
        const int s = kc & 1;
        if (kc >= 2) {
            if (s == 0) { mbar_wait(sb + OFF_MBAR + 0, ph0); ph0 ^= 1; }
            else        { mbar_wait(sb + OFF_MBAR + 8, ph1); ph1 ^= 1; }
        }
        const uint32_t stBase = sb + OFF_STAGE0 + (uint32_t)s * STAGE_PAD;

        // kernel octet (8 fp32) for this segment, per m
        float4 ka[MCNT], kb[MCNT];
        #pragma unroll
        for (int mm = 0; mm < MCNT; mm++) {
            const float* kp = kq + mm * kD + kc * KC + g * 8;
            ka[mm] = *(const float4*)kp;
            kb[mm] = *(const float4*)(kp + 4);
        }

        // ---- A tiles: 4 rows/thread, 8 fp32 -> 8 f16 per m, 16B STS ----
        const float* v1p = v1 + ((size_t)b * kT1 + rb) * kD + kc * KC + g * 8;
        #pragma unroll
        for (int rr = 0; rr < 4; rr++) {
            const float* p = v1p + (size_t)rr * 32 * kD;
            float4 va = *(const float4*)p;
            float4 vb = *(const float4*)(p + 4);
            const int row = rb + rr * 32;
            const uint32_t so = SW128((uint32_t)(row * 128 + g * 16));
            #pragma unroll
            for (int mm = 0; mm < MCNT; mm++) {
                sts128(stBase + mm * A_TILE_B + so,
                       f16x2(va.x * ka[mm].x, va.y * ka[mm].y),
                       f16x2(va.z * ka[mm].z, va.w * ka[mm].w),
                       f16x2(vb.x * kb[mm].x, vb.y * kb[mm].y),
                       f16x2(vb.z * kb[mm].z, vb.w * kb[mm].w));
            }
        }

        // ---- B tile: 80 rows x 8 segments = 640 ----
        for (int idx = tid; idx < NT * 8; idx += 256) {
            const int j = idx >> 3, gg = idx & 7;
            const float* p = v2 + ((size_t)b * kT2 + jt * NT + j) * kD +
                             kc * KC + gg * 8;
            float4 va = *(const float4*)p;
            float4 vb = *(const float4*)(p + 4);
            sts128(stBase + MCNT * A_TILE_B + SW128((uint32_t)(j * 128 + gg * 16)),
                   f16x2(va.x, va.y), f16x2(va.z, va.w),
                   f16x2(vb.x, vb.y), f16x2(vb.z, vb.w));
        }

        // make generic SMEM writes visible to the async (tensor) proxy
        asm volatile("fence.proxy.async.shared::cta;" ::: "memory");
        __syncthreads();

        // ---- issue 16 MMAs (4 K-steps x 4 m) from one thread ----
        if (wid == 0 && elect_one()) {
            const uint64_t bdesc = make_desc(stBase + MCNT * A_TILE_B);
            #pragma unroll
            for (int ks = 0; ks < KSTEPS; ks++) {
                #pragma unroll
                for (int mm = 0; mm < MCNT; mm++) {
                    mma_f16(tmem + mm * NT,
                            make_desc(stBase + mm * A_TILE_B) + ks * 2,
                            bdesc + ks * 2, IDESC,
                            (kc > 0 || ks > 0) ? 1u : 0u);
                }
            }
            tc_commit(sb + OFF_MBAR + (uint32_t)s * 8);
        }
    }

    // ---- drain both stages ----
    mbar_wait(sb + OFF_MBAR + 0, ph0);
    mbar_wait(sb + OFF_MBAR + 8, ph1);
    asm volatile("tcgen05.fence::after_thread_sync;" ::: "memory");
    __syncthreads();

    // ---- epilogue ----
    // warp w: subpartition sp = w&3 -> rows i = sp*32+lane; j-half h = w>>2.
    // Each thread gathers all 4 m accumulators for its (i,j) -> float4 store.
    {
        const int sp = wid & 3;
        const int h  = wid >> 2;
        const uint32_t woff = ((uint32_t)sp) << 21;  // lane-base (sp*32)<<16
        const int i = sp * 32 + lane;
        float* obase = out + (((size_t)b * kT1 + i) * kT2 + (size_t)jt * NT) * kM +
                       (size_t)mg * MCNT;
        for (int jc = 0; jc < 5; jc++) {
            uint32_t acc[MCNT][8];
            #pragma unroll
            for (int mm = 0; mm < MCNT; mm++)
                ldtm_x8(acc[mm], tmem + mm * NT + h * 40 + jc * 8 + woff);
            asm volatile("tcgen05.wait::ld.sync.aligned;" ::: "memory");
            #pragma unroll
            for (int jj = 0; jj < 8; jj++) {
                const int j = h * 40 + jc * 8 + jj;
                float4 o;
                o.x = fast_tanh(__uint_as_float(acc[0][jj]));
                o.y = fast_tanh(__uint_as_float(acc[1][jj]));
                o.z = fast_tanh(__uint_as_float(acc[2][jj]));
                o.w = fast_tanh(__uint_as_float(acc[3][jj]));
                *(float4*)(obase + (size_t)j * kM) = o;
            }
        }
    }

    asm volatile("tcgen05.fence::before_thread_sync;" ::: "memory");
    __syncthreads();
    if (wid == 0) {
        asm volatile("tcgen05.dealloc.cta_group::1.sync.aligned.b32 %0, %1;"
                     :: "r"(tmem), "r"(512u));
    }

#else  // ---------------- non-sm_103a fallback (compiled, never run) --------
    // Same CTA tiling: (b, 4 m, 80 j). Kernel rows cached in SMEM; each thread
    // walks (i,j) pairs, 768-FMA loop per pair, fp16-rounded inputs to match.
    float* ks = (float*)(smem + OFF_KERN);
    for (int i = tid; i < MCNT * kD; i += 256)
        ks[i] = kern[(size_t)(mg * MCNT + i / kD) * kD + (i % kD)];
    __syncthreads();

    for (int idx = tid; idx < kT1 * NT; idx += 256) {
        const int i = idx / NT;
        const int j = jt * NT + idx % NT;
        const float* p1 = v1 + ((size_t)b * kT1 + i) * kD;
        const float* p2 = v2 + ((size_t)b * kT2 + j) * kD;
        float acc[MCNT] = {0.f, 0.f, 0.f, 0.f};
        for (int d = 0; d < kD; d++) {
            const float a = p1[d];
            const float c = f16rt(p2[d]);
            #pragma unroll
            for (int mm = 0; mm < MCNT; mm++)
                acc[mm] = fmaf(f16rt(a * ks[mm * kD + d]), c, acc[mm]);
        }
        float* o = out + (((size_t)b * kT1 + i) * kT2 + j) * kM + (size_t)mg * MCNT;
        #pragma unroll
        for (int mm = 0; mm < MCNT; mm++) o[mm] = fast_tanh(acc[mm]);
    }
#endif
}

extern "C" void kernel_launch(void* const* d_in, const int* in_sizes, int n_in,
                              void* d_out, int out_size) {
    (void)in_sizes; (void)n_in; (void)out_size;
    const float* v1   = (const float*)d_in[0];
    const float* v2   = (const float*)d_in[1];
    const float* kern = (const float*)d_in[2];
    float* out = (float*)d_out;

    cudaFuncSetAttribute(mpc_kernel, cudaFuncAttributeMaxDynamicSharedMemorySize,
                         SMEM_TOTAL);
    // grid: b (64) x m-group (16) x j-tile (2) = 2048 CTAs; consecutive CTAs
    // share b -> v1/v2 stay L2-resident across the m-groups.
    mpc_kernel<<<2048, 256, SMEM_TOTAL>>>(v1, v2, kern, out);
}